// round 3
// baseline (speedup 1.0000x reference)
#include <cuda_runtime.h>
#include <cuda_fp16.h>

#define N_NODES 100000
#define N_EDGES 1600000
#define HID 64
#define SCAN_CHUNK 1024
#define SCAN_BLOCKS ((N_NODES + SCAN_CHUNK - 1) / SCAN_CHUNK)  // 98
#define FULL 0xffffffffu

typedef unsigned long long ull;
struct __align__(16) ull2v { ull x, y; };

// -------- scratch (static device globals; no runtime allocation) --------
__device__ int     g_cursor[N_NODES];       // degree counter / scatter cursor
__device__ int     g_rowoff[N_NODES + 1];
__device__ int     g_psum[SCAN_BLOCKS];
__device__ int     g_rank[N_EDGES];
__device__ int     g_csr[N_EDGES];
__device__ float   g_dinv[N_NODES];
__device__ float4  g_xs[N_NODES];           // dinv[v] * x[v]
__device__ __half2 g_h1[(size_t)N_NODES * 32];  // dinv[v] * relu(layer1) as half2
__device__ int     g_i64;

// -------- packed f32x2 helpers --------
__device__ __forceinline__ ull pk(float a, float b) {
    ull r; asm("mov.b64 %0, {%1,%2};" : "=l"(r) : "f"(a), "f"(b)); return r;
}
__device__ __forceinline__ float2 upk(ull v) {
    float2 r; asm("mov.b64 {%0,%1}, %2;" : "=f"(r.x), "=f"(r.y) : "l"(v)); return r;
}
#define FFMA2(acc, a, b) \
    asm("fma.rn.f32x2 %0, %1, %2, %3;" : "=l"(acc) : "l"(a), "l"(b), "l"(acc))

__device__ __forceinline__ int load_idx(const void* ei, long long pos, int is64) {
    if (is64) return (int)((const long long*)ei)[pos];
    return ((const int*)ei)[pos];
}

// -------- init: zero cursors, block 0 also detects index dtype --------
__global__ void k_init(const void* __restrict__ ei) {
    int t = threadIdx.x;                     // 1024 threads
    if (blockIdx.x == 0) {
        int v = ((const int*)ei)[2 * t + 1]; // hi word if i64, random id if i32
        int any = __syncthreads_or(v != 0);
        if (t == 0) g_i64 = any ? 0 : 1;
    }
    int i = blockIdx.x * blockDim.x + t;
    int stride = gridDim.x * blockDim.x;
    for (int n = i; n < N_NODES; n += stride) g_cursor[n] = 0;
}

// -------- pass A: per-edge rank via single atomic (cursor becomes degree) --------
__global__ void k_passA(const void* __restrict__ ei) {
    int is64 = g_i64;
    int i = blockIdx.x * blockDim.x + threadIdx.x;
    int stride = gridDim.x * blockDim.x;
    for (int e = i; e < N_EDGES; e += stride) {
        int d = load_idx(ei, (long long)N_EDGES + e, is64);
        g_rank[e] = atomicAdd(&g_cursor[d], 1);
    }
}

// -------- scan (local) + dinv + pre-scaled x --------
__global__ void k_scan_local(const float* __restrict__ x) {
    __shared__ int sm[SCAN_CHUNK];
    int t = threadIdx.x;
    int idx = blockIdx.x * SCAN_CHUNK + t;
    int v = (idx < N_NODES) ? g_cursor[idx] : 0;
    if (idx < N_NODES) {
        float di = rsqrtf((float)(v + 1));   // +1 self loop
        g_dinv[idx] = di;
        float4 xv = ((const float4*)x)[idx];
        xv.x *= di; xv.y *= di; xv.z *= di; xv.w *= di;
        g_xs[idx] = xv;
    }
    sm[t] = v;
    __syncthreads();
    for (int o = 1; o < SCAN_CHUNK; o <<= 1) {
        int add = (t >= o) ? sm[t - o] : 0;
        __syncthreads();
        sm[t] += add;
        __syncthreads();
    }
    if (idx < N_NODES) g_rowoff[idx] = sm[t] - v;
    if (t == SCAN_CHUNK - 1) g_psum[blockIdx.x] = sm[t];
}

__global__ void k_scan_top() {   // 1 block, 128 threads
    __shared__ int sm[128];
    int t = threadIdx.x;
    int v = (t < SCAN_BLOCKS) ? g_psum[t] : 0;
    sm[t] = v;
    __syncthreads();
    for (int o = 1; o < 128; o <<= 1) {
        int add = (t >= o) ? sm[t - o] : 0;
        __syncthreads();
        sm[t] += add;
        __syncthreads();
    }
    if (t < SCAN_BLOCKS) g_psum[t] = sm[t] - v;
    if (t == 127) g_rowoff[N_NODES] = sm[127];
}

__global__ void k_scan_add() {
    int i = blockIdx.x * blockDim.x + threadIdx.x;
    int stride = gridDim.x * blockDim.x;
    for (int n = i; n < N_NODES; n += stride)
        g_rowoff[n] += g_psum[n / SCAN_CHUNK];
}

// -------- pass B: scatter into CSR, no atomics --------
__global__ void k_passB(const void* __restrict__ ei) {
    int is64 = g_i64;
    int i = blockIdx.x * blockDim.x + threadIdx.x;
    int stride = gridDim.x * blockDim.x;
    for (int e = i; e < N_EDGES; e += stride) {
        int s = load_idx(ei, e, is64);
        int d = load_idx(ei, (long long)N_EDGES + e, is64);
        g_csr[g_rowoff[d] + g_rank[e]] = s;
    }
}

// -------- layer 1: aggregate pre-scaled 4-dim x, 4x64 transform, ReLU,
//          store dinv[d]-scaled result as half2 (features 2*lane, 2*lane+1) --------
__global__ void k_layer1(const float* __restrict__ W1,
                         const float* __restrict__ b1) {
    __shared__ float2 sW[4 * 32];
    __shared__ float2 sb[32];
    int t = threadIdx.x;                 // 256 threads
    if (t < 128) {
        int k = t >> 5, l = t & 31;
        sW[t] = make_float2(W1[k * HID + 2 * l], W1[k * HID + 2 * l + 1]);
    }
    if (t < 32) sb[t] = make_float2(b1[2 * t], b1[2 * t + 1]);
    __syncthreads();
    int warp = (blockIdx.x * blockDim.x + t) >> 5;
    int lane = t & 31;
    if (warp >= N_NODES) return;
    int d = warp;
    int beg = g_rowoff[d], end = g_rowoff[d + 1];
    float a0 = 0.f, a1 = 0.f, a2 = 0.f, a3 = 0.f;
    for (int i = beg + lane; i < end; i += 32) {
        int s = g_csr[i];
        float4 v = g_xs[s];
        a0 += v.x; a1 += v.y; a2 += v.z; a3 += v.w;
    }
#pragma unroll
    for (int o = 16; o; o >>= 1) {
        a0 += __shfl_xor_sync(FULL, a0, o);
        a1 += __shfl_xor_sync(FULL, a1, o);
        a2 += __shfl_xor_sync(FULL, a2, o);
        a3 += __shfl_xor_sync(FULL, a3, o);
    }
    float dd = g_dinv[d];
    float4 vd = g_xs[d];
    a0 = dd * (a0 + vd.x);
    a1 = dd * (a1 + vd.y);
    a2 = dd * (a2 + vd.z);
    a3 = dd * (a3 + vd.w);
    float2 w0 = sW[lane], w1 = sW[32 + lane], w2 = sW[64 + lane], w3 = sW[96 + lane];
    float2 bb = sb[lane];
    float o0 = bb.x + a0 * w0.x + a1 * w1.x + a2 * w2.x + a3 * w3.x;
    float o1 = bb.y + a0 * w0.y + a1 * w1.y + a2 * w2.y + a3 * w3.y;
    o0 = fmaxf(o0, 0.f) * dd;            // pre-scale by dinv[d] for layer 2
    o1 = fmaxf(o1, 0.f) * dd;
    g_h1[(size_t)d * 32 + lane] = __floats2half2_rn(o0, o1);
}

// -------- layer 2: fp16 gather-sum, packed-f32x2 64x64 matmul, ReLU, head --------
// sW2 layout (k-major pairs per column, padded): column c occupies 17 ull2 slots;
// slot k4 holds pairs {(W2[4k4][c],W2[4k4+1][c]), (W2[4k4+2][c],W2[4k4+3][c])}
__global__ void k_layer2(const float* __restrict__ W2,
                         const float* __restrict__ b2,
                         const float* __restrict__ Wl,
                         const float* __restrict__ bl,
                         float* __restrict__ out) {
    __shared__ ull2v sW2[HID * 17];      // 17408 B
    __shared__ ull2v sAgg[8][16];        // 2048 B, 8 warps/block
    int t = threadIdx.x;                 // 256 threads
    for (int i = t; i < HID * 16; i += 256) {
        int c = i >> 4, k4 = i & 15;
        ull2v e;
        e.x = pk(W2[(4 * k4) * HID + c],     W2[(4 * k4 + 1) * HID + c]);
        e.y = pk(W2[(4 * k4 + 2) * HID + c], W2[(4 * k4 + 3) * HID + c]);
        sW2[c * 17 + k4] = e;
    }
    __syncthreads();
    int warp = (blockIdx.x * blockDim.x + t) >> 5;
    int lane = t & 31;
    int wib = t >> 5;
    if (warp >= N_NODES) return;
    int d = warp;
    int beg = g_rowoff[d], end = g_rowoff[d + 1];
    float ax = 0.f, ay = 0.f;
    for (int base = beg; base < end; base += 32) {
        int n = end - base; if (n > 32) n = 32;
        int myidx = (base + lane < end) ? g_csr[base + lane] : 0;
        for (int j = 0; j < n; j++) {
            int s = __shfl_sync(FULL, myidx, j);
            float2 v = __half22float2(g_h1[(size_t)s * 32 + lane]);
            ax += v.x; ay += v.y;
        }
    }
    {   // self loop (h1 already dinv[d]-scaled), then dst factor
        float2 v = __half22float2(g_h1[(size_t)d * 32 + lane]);
        float dd = g_dinv[d];
        ax = dd * (ax + v.x);
        ay = dd * (ay + v.y);
    }
    ((ull*)sAgg[wib])[lane] = pk(ax, ay);
    __syncwarp();
    ull accl0 = 0, accl1 = 0, acch0 = 0, acch1 = 0;
    const ull2v* ap = sAgg[wib];
    const ull2v* wl_ = &sW2[lane * 17];
    const ull2v* wh_ = &sW2[(lane + 32) * 17];
#pragma unroll
    for (int k4 = 0; k4 < 16; k4++) {
        ull2v aa = ap[k4];
        ull2v wa = wl_[k4];
        ull2v wb = wh_[k4];
        FFMA2(accl0, aa.x, wa.x);
        FFMA2(accl1, aa.y, wa.y);
        FFMA2(acch0, aa.x, wb.x);
        FFMA2(acch1, aa.y, wb.y);
    }
    float2 u;
    float o0, o1;
    u = upk(accl0); o0 = u.x + u.y;
    u = upk(accl1); o0 += u.x + u.y;
    o0 += b2[lane];
    u = upk(acch0); o1 = u.x + u.y;
    u = upk(acch1); o1 += u.x + u.y;
    o1 += b2[lane + 32];
    o0 = fmaxf(o0, 0.f);
    o1 = fmaxf(o1, 0.f);
    float p = o0 * Wl[lane] + o1 * Wl[lane + 32];
#pragma unroll
    for (int o = 16; o; o >>= 1) p += __shfl_xor_sync(FULL, p, o);
    if (lane == 0) out[d] = p + bl[0];
}

extern "C" void kernel_launch(void* const* d_in, const int* in_sizes, int n_in,
                              void* d_out, int out_size) {
    const float* x  = (const float*)d_in[0];
    const void*  ei = d_in[1];
    const float* W1 = (const float*)d_in[2];
    const float* b1 = (const float*)d_in[3];
    const float* W2 = (const float*)d_in[4];
    const float* b2 = (const float*)d_in[5];
    const float* Wl = (const float*)d_in[6];
    const float* bl = (const float*)d_in[7];
    float* out = (float*)d_out;

    (void)x; (void)in_sizes; (void)n_in; (void)out_size;

    k_init<<<100, 1024>>>(ei);
    k_passA<<<2048, 256>>>(ei);
    k_scan_local<<<SCAN_BLOCKS, SCAN_CHUNK>>>(x);
    k_scan_top<<<1, 128>>>();
    k_scan_add<<<200, 512>>>();
    k_passB<<<2048, 256>>>(ei);

    int blocks = (N_NODES * 32 + 255) / 256;   // warp per node
    k_layer1<<<blocks, 256>>>(W1, b1);
    k_layer2<<<blocks, 256>>>(W2, b2, Wl, bl, out);
}